// round 14
// baseline (speedup 1.0000x reference)
#include <cuda_runtime.h>
#include <cuda_bf16.h>
#include <cstdint>

// LSTMModel: B=4096, T=512, D=8, H=64, 2 layers + FC(64->1)
//
// R11 = R8 microstructure (256 thr, fat threads) + 148-block redistribution:
//  - 2048 batch-pairs over 148 blocks: 124 x 14 pairs + 24 x 13 pairs.
//  - Groups within a block get {4,4,3,3} ({4,3,3,3}) pairs -> every SMSP
//    carries exactly 7 pairs (was 8), all 148 SMs busy. fma floor -12.5%.
//  - Pair count P is warp-uniform -> T-loop templated on P (4 or 3); both
//    instances hit the same 3-barrier-per-step sequence (arrival-counted).
//  - Phases per step: A(z0) | bar | C(z1+=Whh1@h1_old interleaved w/ cell0,
//    stage x) | bar | E(z1+=Wih1@h0_new) | bar | F(cell1, overlaps next A).

#define ULL unsigned long long

static __device__ __forceinline__ ULL pk2(float v) {
    ULL r; asm("mov.b64 %0, {%1, %1};" : "=l"(r) : "f"(v)); return r;
}
static __device__ __forceinline__ ULL pkf2(float a, float b) {
    ULL r; asm("mov.b64 %0, {%1, %2};" : "=l"(r) : "f"(a), "f"(b)); return r;
}
static __device__ __forceinline__ float2 upk(ULL v) {
    float2 f; asm("mov.b64 {%0, %1}, %2;" : "=f"(f.x), "=f"(f.y) : "l"(v)); return f;
}
static __device__ __forceinline__ ULL ffma2(ULL a, ULL b, ULL c) {
    ULL d; asm("fma.rn.f32x2 %0, %1, %2, %3;" : "=l"(d) : "l"(a), "l"(b), "l"(c)); return d;
}
static __device__ __forceinline__ float ex2f(float x) {
    float r; asm("ex2.approx.f32 %0, %1;" : "=f"(r) : "f"(x)); return r;
}
static __device__ __forceinline__ float rcpf(float x) {
    float r; asm("rcp.approx.f32 %0, %1;" : "=f"(r) : "f"(x)); return r;
}
static __device__ __forceinline__ float sigm(float x) {
    return rcpf(1.0f + ex2f(-1.4426950408889634f * x));
}
static __device__ __forceinline__ float tanh_fast(float x) {
    float ax = fabsf(x);
    float p = ex2f(-2.8853900817779268f * ax);
    float r = (1.0f - p) * rcpf(1.0f + p);
    return copysignf(r, x);
}

static constexpr int B = 4096;
static constexpr int T = 512;
static constexpr int D = 8;
static constexpr int NBLOCKS = 148;       // 124*14 + 24*13 = 2048 pairs
static constexpr int NTHREADS = 256;
static constexpr int HSTRIDE = 36;        // padded row stride (floats)

// smem float offsets (R3/R8 layout)
static constexpr int OFF_WIH0 = 0;                    //  8*256
static constexpr int OFF_WHH0 = OFF_WIH0 + 2048;      // 64*256
static constexpr int OFF_WIH1 = OFF_WHH0 + 16384;
static constexpr int OFF_WHH1 = OFF_WIH1 + 16384;
static constexpr int OFF_B0   = OFF_WHH1 + 16384;     // 256
static constexpr int OFF_B1   = OFF_B0 + 256;         // 256
static constexpr int OFF_WFC  = OFF_B1 + 256;         // 64
static constexpr int OFF_H0   = OFF_WFC + 64;         // 64*36
static constexpr int OFF_H1   = OFF_H0 + 64 * HSTRIDE;
static constexpr int OFF_XS   = OFF_H1 + 64 * HSTRIDE;// 2*256
static constexpr int SMEM_FLOATS = OFF_XS + 512;
static constexpr int SMEM_BYTES = SMEM_FLOATS * 4;    // 227,584 B

extern __shared__ float sm[];

// Accumulate 4 gates x P batch-pairs from one k-slice into a[q*P+p].
template<int P>
static __device__ __forceinline__ void acc_step(ULL (&a)[4 * P],
                                                const float* __restrict__ wb,
                                                const float* __restrict__ hb) {
    float4 w = *(const float4*)(wb);
    ULL wq0 = pk2(w.x), wq1 = pk2(w.y), wq2 = pk2(w.z), wq3 = pk2(w.w);
    ULL h[P];
    if constexpr (P == 4) {
        ulonglong2 hA = *(const ulonglong2*)(hb);
        ulonglong2 hB = *(const ulonglong2*)(hb + 4);
        h[0] = hA.x; h[1] = hA.y; h[2] = hB.x; h[3] = hB.y;
    } else {
        #pragma unroll
        for (int p = 0; p < P; ++p) h[p] = *(const ULL*)(hb + 2 * p);
    }
    #pragma unroll
    for (int p = 0; p < P; ++p) {
        a[0 * P + p] = ffma2(wq0, h[p], a[0 * P + p]);
        a[1 * P + p] = ffma2(wq1, h[p], a[1 * P + p]);
        a[2 * P + p] = ffma2(wq2, h[p], a[2 * P + p]);
        a[3 * P + p] = ffma2(wq3, h[p], a[3 * P + p]);
    }
}

template<int P>
static __device__ __forceinline__ void init_acc(ULL (&a)[4 * P], float4 bz) {
    ULL bi = pk2(bz.x), bf = pk2(bz.y), bg = pk2(bz.z), bo = pk2(bz.w);
    #pragma unroll
    for (int p = 0; p < P; ++p) {
        a[0 * P + p] = bi; a[1 * P + p] = bf;
        a[2 * P + p] = bg; a[3 * P + p] = bo;
    }
}

// LSTM cell for batch-pair p. Returns packed h, updates packed c.
template<int P>
static __device__ __forceinline__ ULL cell_pair(const ULL (&a)[4 * P], int p, ULL& c) {
    float2 i2 = upk(a[p]), f2 = upk(a[P + p]);
    float2 g2 = upk(a[2 * P + p]), o2 = upk(a[3 * P + p]);
    float2 c2 = upk(c);
    float i0 = sigm(i2.x), f0 = sigm(f2.x), g0 = tanh_fast(g2.x), o0 = sigm(o2.x);
    float i1 = sigm(i2.y), f1 = sigm(f2.y), g1 = tanh_fast(g2.y), o1 = sigm(o2.y);
    float cn0 = f0 * c2.x + i0 * g0;
    float cn1 = f1 * c2.y + i1 * g1;
    c = pkf2(cn0, cn1);
    return pkf2(o0 * tanh_fast(cn0), o1 * tanh_fast(cn1));
}

// The full T-step recurrence for one thread owning P batch-pairs.
template<int P>
static __device__ void lstm_T(int jw, int hoff, int bl, int dl, bool xv,
                              const float* __restrict__ xptr,
                              float4 b0v, float4 b1v,
                              float* __restrict__ h0dst, float* __restrict__ h1dst)
{
    ULL c0[P], c1[P];
    #pragma unroll
    for (int p = 0; p < P; ++p) { c0[p] = 0ULL; c1[p] = 0ULL; }

    ULL a0[4 * P], a1[4 * P];

    for (int t = 0; t < T; ++t) {
        const int cur = (t & 1) * 256;
        const int nxt = 256 - cur;
        float xn = 0.0f;
        if (xv && t + 1 < T) xn = __ldg(xptr + (t + 1) * D);

        // ---------- phase A: z0 = x@Wih0^T + h0_old@Whh0^T ----------
        init_acc<P>(a0, b0v);
        #pragma unroll
        for (int d = 0; d < D; ++d)
            acc_step<P>(a0, sm + OFF_WIH0 + d * 256 + jw, sm + OFF_XS + cur + d * 32 + hoff);
        #pragma unroll 8
        for (int k = 0; k < 64; ++k)
            acc_step<P>(a0, sm + OFF_WHH0 + k * 256 + jw, sm + OFF_H0 + k * HSTRIDE + hoff);

        __syncthreads();   // bar1: reads of h0_old + xs(cur) done; F(t-1) writes fenced

        // ---------- phase C: z1 += Whh1@h1_old, interleaved with cell0 ----------
        init_acc<P>(a1, b1v);
        #pragma unroll
        for (int p = 0; p < P; ++p) {
            const int k0 = (p * 64) / P, k1 = ((p + 1) * 64) / P;
            #pragma unroll
            for (int k = k0; k < k1; ++k)
                acc_step<P>(a1, sm + OFF_WHH1 + k * 256 + jw, sm + OFF_H1 + k * HSTRIDE + hoff);
            *(ULL*)(h0dst + 2 * p) = cell_pair<P>(a0, p, c0[p]);
        }
        if (xv) sm[OFF_XS + nxt + dl * 32 + bl] = xn;   // stage next x

        __syncthreads();   // bar2: h0_new + xs(next) visible; h1_old reads done

        // ---------- phase E: z1 += Wih1@h0_new ----------
        #pragma unroll 8
        for (int k = 0; k < 64; ++k)
            acc_step<P>(a1, sm + OFF_WIH1 + k * 256 + jw, sm + OFF_H0 + k * HSTRIDE + hoff);

        __syncthreads();   // bar3: all z1 inputs consumed

        // ---------- phase F: cell1 -> h1 (overlaps next step's phase A) ----------
        #pragma unroll
        for (int p = 0; p < P; ++p)
            *(ULL*)(h1dst + 2 * p) = cell_pair<P>(a1, p, c1[p]);
        // no trailing barrier: next A reads only h0/xs; C(t+1) fenced by bar1.
    }
}

__global__ void __launch_bounds__(NTHREADS, 1)
lstm_kernel(const float* __restrict__ x,
            const float* __restrict__ Wih0, const float* __restrict__ Whh0,
            const float* __restrict__ bih0, const float* __restrict__ bhh0,
            const float* __restrict__ Wih1, const float* __restrict__ Whh1,
            const float* __restrict__ bih1, const float* __restrict__ bhh1,
            const float* __restrict__ Wfc,  const float* __restrict__ bfc,
            float* __restrict__ out)
{
    const int tid = threadIdx.x;
    const int j = tid & 63;        // hidden unit
    const int g = tid >> 6;        // group 0..3

    // ---- block -> batch-pair partition: 124 blocks x 14 pairs, 24 x 13 ----
    const int b = blockIdx.x;
    const bool big = (b < 124);
    const int npairs = big ? 14 : 13;
    const int pair_base = big ? b * 14 : 1736 + (b - 124) * 13;
    const int batch_base = pair_base * 2;
    const int nbatch = npairs * 2;
    const int extra = npairs - 12;                 // groups with 4 pairs
    const int offs_g = 3 * g + (g < extra ? g : extra);
    const int P_g = (g < extra) ? 4 : 3;
    const int hoff = offs_g * 2;                   // float offset in h/x rows

    // ---- load + transpose weights into smem ----
    for (int idx = tid; idx < 2048; idx += NTHREADS) {
        int d = idx >> 8, r = idx & 255, jj = r >> 2, q = r & 3;
        sm[OFF_WIH0 + idx] = Wih0[(q * 64 + jj) * 8 + d];
    }
    for (int idx = tid; idx < 16384; idx += NTHREADS) {
        int k = idx >> 8, r = idx & 255, jj = r >> 2, q = r & 3;
        int row = (q * 64 + jj) * 64 + k;
        sm[OFF_WHH0 + idx] = Whh0[row];
        sm[OFF_WIH1 + idx] = Wih1[row];
        sm[OFF_WHH1 + idx] = Whh1[row];
    }
    {
        int jj = tid >> 2, q = tid & 3;
        sm[OFF_B0 + tid] = bih0[q * 64 + jj] + bhh0[q * 64 + jj];
        sm[OFF_B1 + tid] = bih1[q * 64 + jj] + bhh1[q * 64 + jj];
    }
    if (tid < 64) sm[OFF_WFC + tid] = Wfc[tid];
    for (int idx = tid; idx < 2 * 64 * HSTRIDE; idx += NTHREADS)
        sm[OFF_H0 + idx] = 0.0f;   // zero h0 and h1 (contiguous)

    // x prefetch mapping: thread loads x[batch_base + bl][t][dl], bl < nbatch
    const int bl = tid >> 3;       // 0..31
    const int dl = tid & 7;        // 0..7
    const bool xv = (bl < nbatch);
    const float* xptr = x + (size_t)(batch_base + (xv ? bl : 0)) * (T * D) + dl;
    float x0 = xv ? __ldg(xptr) : 0.0f;
    __syncthreads();               // weight/bias writes visible
    if (xv) sm[OFF_XS + dl * 32 + bl] = x0;

    float* h0dst = sm + OFF_H0 + j * HSTRIDE + hoff;
    float* h1dst = sm + OFF_H1 + j * HSTRIDE + hoff;
    const float4 b0v = *(const float4*)(sm + OFF_B0 + j * 4);
    const float4 b1v = *(const float4*)(sm + OFF_B1 + j * 4);
    const int jw = j * 4;

    __syncthreads();               // x stage for t=0 visible

    // warp-uniform dispatch (g constant per warp); both instances execute the
    // same count of __syncthreads per iteration (arrival-counted on sm_70+).
    if (P_g == 4) lstm_T<4>(jw, hoff, bl, dl, xv, xptr, b0v, b1v, h0dst, h1dst);
    else          lstm_T<3>(jw, hoff, bl, dl, xv, xptr, b0v, b1v, h0dst, h1dst);

    __syncthreads();               // final h1 visible

    // ---------- FC head: out[b] = h1[b] . Wfc + bfc ----------
    if (tid < nbatch) {
        float acc2 = __ldg(bfc);
        #pragma unroll 8
        for (int k = 0; k < 64; ++k)
            acc2 += sm[OFF_H1 + k * HSTRIDE + tid] * sm[OFF_WFC + k];
        out[batch_base + tid] = acc2;
    }
}

extern "C" void kernel_launch(void* const* d_in, const int* in_sizes, int n_in,
                              void* d_out, int out_size) {
    (void)in_sizes; (void)n_in; (void)out_size;
    const float* x    = (const float*)d_in[0];
    const float* Wih0 = (const float*)d_in[1];
    const float* Whh0 = (const float*)d_in[2];
    const float* bih0 = (const float*)d_in[3];
    const float* bhh0 = (const float*)d_in[4];
    const float* Wih1 = (const float*)d_in[5];
    const float* Whh1 = (const float*)d_in[6];
    const float* bih1 = (const float*)d_in[7];
    const float* bhh1 = (const float*)d_in[8];
    const float* Wfc  = (const float*)d_in[9];
    const float* bfc  = (const float*)d_in[10];
    float* out = (float*)d_out;

    cudaFuncSetAttribute(lstm_kernel,
                         cudaFuncAttributeMaxDynamicSharedMemorySize, SMEM_BYTES);
    lstm_kernel<<<NBLOCKS, NTHREADS, SMEM_BYTES>>>(
        x, Wih0, Whh0, bih0, bhh0, Wih1, Whh1, bih1, bhh1, Wfc, bfc, out);
}

// round 16
// speedup vs baseline: 1.4230x; 1.4230x over previous
#include <cuda_runtime.h>
#include <cuda_bf16.h>
#include <cstdint>

// LSTMModel: B=4096, T=512, D=8, H=64, 2 layers + FC(64->1)
//
// R15 = R8 (best: 4542us) with exactly two changes:
//  1. Warp re-composition: j = tid>>2, g = tid&3 (warp = 8 j x 4 g).
//     Weight LDS.128 becomes a 4-way broadcast over 8 float4 = 1 wavefront
//     (was 32 distinct float4 = 4 wavefronts). Smem traffic per step halves
//     (9600 -> 4800 wf; measured L1=60.6% said the crossbar was starving fma).
//     All smem layouts / math / f32x2 packing are byte-identical to R8.
//  2. bar3 deleted (F's h1 writes are disjoint from E and A(t+1) reads; first
//     h1 reader is C(t+1), fenced by bar1(t+1)). 2 barriers/step.
//
//  Phases per step: A(z0) | bar1 | C(z1+=Whh1@h1_old interleaved w/ cell0,
//  stage x) | bar2 | E(z1+=Wih1@h0_new) | F(cell1 -> h1, overlaps next A).

#define ULL unsigned long long

static __device__ __forceinline__ ULL pk2(float v) {
    ULL r; asm("mov.b64 %0, {%1, %1};" : "=l"(r) : "f"(v)); return r;
}
static __device__ __forceinline__ ULL pkf2(float a, float b) {
    ULL r; asm("mov.b64 %0, {%1, %2};" : "=l"(r) : "f"(a), "f"(b)); return r;
}
static __device__ __forceinline__ float2 upk(ULL v) {
    float2 f; asm("mov.b64 {%0, %1}, %2;" : "=f"(f.x), "=f"(f.y) : "l"(v)); return f;
}
static __device__ __forceinline__ ULL ffma2(ULL a, ULL b, ULL c) {
    ULL d; asm("fma.rn.f32x2 %0, %1, %2, %3;" : "=l"(d) : "l"(a), "l"(b), "l"(c)); return d;
}
static __device__ __forceinline__ float ex2f(float x) {
    float r; asm("ex2.approx.f32 %0, %1;" : "=f"(r) : "f"(x)); return r;
}
static __device__ __forceinline__ float rcpf(float x) {
    float r; asm("rcp.approx.f32 %0, %1;" : "=f"(r) : "f"(x)); return r;
}
static __device__ __forceinline__ float sigm(float x) {
    return rcpf(1.0f + ex2f(-1.4426950408889634f * x));
}
static __device__ __forceinline__ float tanh_fast(float x) {
    float ax = fabsf(x);
    float p = ex2f(-2.8853900817779268f * ax);
    float r = (1.0f - p) * rcpf(1.0f + p);
    return copysignf(r, x);
}

static constexpr int B = 4096;
static constexpr int T = 512;
static constexpr int D = 8;
static constexpr int NBATCH_BLK = 32;
static constexpr int NTHREADS = 256;
static constexpr int HSTRIDE = 36;      // padded row stride (floats) for h state

// smem float offsets (identical to R3/R8)
static constexpr int OFF_WIH0 = 0;                    //  8*256
static constexpr int OFF_WHH0 = OFF_WIH0 + 2048;      // 64*256
static constexpr int OFF_WIH1 = OFF_WHH0 + 16384;     // 64*256
static constexpr int OFF_WHH1 = OFF_WIH1 + 16384;     // 64*256
static constexpr int OFF_B0   = OFF_WHH1 + 16384;     // 256
static constexpr int OFF_B1   = OFF_B0 + 256;         // 256
static constexpr int OFF_WFC  = OFF_B1 + 256;         // 64
static constexpr int OFF_H0   = OFF_WFC + 64;         // 64*36
static constexpr int OFF_H1   = OFF_H0 + 64 * HSTRIDE;// 64*36
static constexpr int OFF_XS   = OFF_H1 + 64 * HSTRIDE;// 2*256
static constexpr int SMEM_FLOATS = OFF_XS + 512;
static constexpr int SMEM_BYTES = SMEM_FLOATS * 4;    // 227,584 B

// Accumulate 4 gates x 4 batch-pairs from one k-slice into a[q*4+p].
// wb: &W[k][j*4] (LDS.128, 4-way broadcast -> 1 wf)
// hb: 4 pairs (2x LDS.128, 4 addrs -> 1 wf each)
static __device__ __forceinline__ void acc_step(ULL (&a)[16],
                                                const float* __restrict__ wb,
                                                const float* __restrict__ hb) {
    float4 w = *(const float4*)(wb);
    ulonglong2 hA = *(const ulonglong2*)(hb);
    ulonglong2 hB = *(const ulonglong2*)(hb + 4);
    ULL h0 = hA.x, h1 = hA.y, h2 = hB.x, h3 = hB.y;
    ULL w0 = pk2(w.x), w1 = pk2(w.y), w2 = pk2(w.z), w3 = pk2(w.w);
    a[0]  = ffma2(w0, h0, a[0]);  a[1]  = ffma2(w0, h1, a[1]);
    a[2]  = ffma2(w0, h2, a[2]);  a[3]  = ffma2(w0, h3, a[3]);
    a[4]  = ffma2(w1, h0, a[4]);  a[5]  = ffma2(w1, h1, a[5]);
    a[6]  = ffma2(w1, h2, a[6]);  a[7]  = ffma2(w1, h3, a[7]);
    a[8]  = ffma2(w2, h0, a[8]);  a[9]  = ffma2(w2, h1, a[9]);
    a[10] = ffma2(w2, h2, a[10]); a[11] = ffma2(w2, h3, a[11]);
    a[12] = ffma2(w3, h0, a[12]); a[13] = ffma2(w3, h1, a[13]);
    a[14] = ffma2(w3, h2, a[14]); a[15] = ffma2(w3, h3, a[15]);
}

static __device__ __forceinline__ void init_acc(ULL (&a)[16], float4 bz) {
    ULL bi = pk2(bz.x), bf = pk2(bz.y), bg = pk2(bz.z), bo = pk2(bz.w);
    a[0] = a[1] = a[2] = a[3] = bi;
    a[4] = a[5] = a[6] = a[7] = bf;
    a[8] = a[9] = a[10] = a[11] = bg;
    a[12] = a[13] = a[14] = a[15] = bo;
}

// LSTM cell for one batch-pair p. Returns packed h, updates packed c.
static __device__ __forceinline__ ULL cell_pair(const ULL (&a)[16], int p, ULL& c) {
    float2 i2 = upk(a[p]), f2 = upk(a[4 + p]), g2 = upk(a[8 + p]), o2 = upk(a[12 + p]);
    float2 c2 = upk(c);
    float i0 = sigm(i2.x), f0 = sigm(f2.x), g0 = tanh_fast(g2.x), o0 = sigm(o2.x);
    float i1 = sigm(i2.y), f1 = sigm(f2.y), g1 = tanh_fast(g2.y), o1 = sigm(o2.y);
    float cn0 = f0 * c2.x + i0 * g0;
    float cn1 = f1 * c2.y + i1 * g1;
    c = pkf2(cn0, cn1);
    return pkf2(o0 * tanh_fast(cn0), o1 * tanh_fast(cn1));
}

extern __shared__ float sm[];

__global__ void __launch_bounds__(NTHREADS, 1)
lstm_kernel(const float* __restrict__ x,
            const float* __restrict__ Wih0, const float* __restrict__ Whh0,
            const float* __restrict__ bih0, const float* __restrict__ bhh0,
            const float* __restrict__ Wih1, const float* __restrict__ Whh1,
            const float* __restrict__ bih1, const float* __restrict__ bhh1,
            const float* __restrict__ Wfc,  const float* __restrict__ bfc,
            float* __restrict__ out)
{
    const int tid = threadIdx.x;
    const int j = tid >> 2;        // hidden unit (warp covers 8 j ...)
    const int g = tid & 3;         // batch group (... x 4 g: broadcast-friendly)
    const int Bb = blockIdx.x * NBATCH_BLK;

    // ---- load + transpose weights into smem (R3/R8 layout) ----
    for (int idx = tid; idx < 2048; idx += NTHREADS) {
        int d = idx >> 8, r = idx & 255, jj = r >> 2, q = r & 3;
        sm[OFF_WIH0 + idx] = Wih0[(q * 64 + jj) * 8 + d];
    }
    for (int idx = tid; idx < 16384; idx += NTHREADS) {
        int k = idx >> 8, r = idx & 255, jj = r >> 2, q = r & 3;
        int row = (q * 64 + jj) * 64 + k;
        sm[OFF_WHH0 + idx] = Whh0[row];
        sm[OFF_WIH1 + idx] = Wih1[row];
        sm[OFF_WHH1 + idx] = Whh1[row];
    }
    {
        int jj = tid >> 2, q = tid & 3;
        sm[OFF_B0 + tid] = bih0[q * 64 + jj] + bhh0[q * 64 + jj];
        sm[OFF_B1 + tid] = bih1[q * 64 + jj] + bhh1[q * 64 + jj];
    }
    if (tid < 64) sm[OFF_WFC + tid] = Wfc[tid];
    for (int idx = tid; idx < 2 * 64 * HSTRIDE; idx += NTHREADS)
        sm[OFF_H0 + idx] = 0.0f;   // zero h0 and h1 (contiguous)

    // x prefetch mapping: thread loads x[Bb + bl][t][dl]
    const int bl = tid >> 3;       // 0..31
    const int dl = tid & 7;        // 0..7
    const float* xptr = x + (size_t)(Bb + bl) * (T * D) + dl;
    float x0 = __ldg(xptr);        // t = 0
    __syncthreads();
    sm[OFF_XS + dl * 32 + bl] = x0;

    ULL c0[4] = {0, 0, 0, 0};      // packed cell state, layer 0 (4 pairs)
    ULL c1[4] = {0, 0, 0, 0};      // layer 1

    const int hoff = g * 8;        // float offset of this group's 4 pairs
    float* h0dst = sm + OFF_H0 + j * HSTRIDE + hoff;
    float* h1dst = sm + OFF_H1 + j * HSTRIDE + hoff;
    const float4 b0v = *(const float4*)(sm + OFF_B0 + j * 4);
    const float4 b1v = *(const float4*)(sm + OFF_B1 + j * 4);
    const int jw = j * 4;

    __syncthreads();   // weights + x stage for t=0 visible

    ULL a0[16], a1[16];

    for (int t = 0; t < T; ++t) {
        const int cur = (t & 1) * 256;
        const int nxt = 256 - cur;
        float xn = 0.0f;
        if (t + 1 < T) xn = __ldg(xptr + (t + 1) * D);

        // ---------- phase A: z0 = x@Wih0^T + h0_old@Whh0^T ----------
        init_acc(a0, b0v);
        #pragma unroll
        for (int d = 0; d < D; ++d)
            acc_step(a0, sm + OFF_WIH0 + d * 256 + jw, sm + OFF_XS + cur + d * 32 + hoff);
        #pragma unroll 8
        for (int k = 0; k < 64; ++k)
            acc_step(a0, sm + OFF_WHH0 + k * 256 + jw, sm + OFF_H0 + k * HSTRIDE + hoff);

        __syncthreads();   // bar1: reads of h0_old + xs(cur) done; F(t-1) h1 writes fenced

        // ---------- phase C: z1 += Whh1@h1_old, interleaved with cell0 ----------
        init_acc(a1, b1v);
        #pragma unroll
        for (int p = 0; p < 4; ++p) {
            #pragma unroll
            for (int k = p * 16; k < p * 16 + 16; ++k)
                acc_step(a1, sm + OFF_WHH1 + k * 256 + jw, sm + OFF_H1 + k * HSTRIDE + hoff);
            ULL hp = cell_pair(a0, p, c0[p]);
            *(ULL*)(h0dst + 2 * p) = hp;
        }
        sm[OFF_XS + nxt + dl * 32 + bl] = xn;   // stage next x

        __syncthreads();   // bar2: h0_new + xs(next) visible; h1_old reads done

        // ---------- phase E: z1 += Wih1@h0_new ----------
        #pragma unroll 8
        for (int k = 0; k < 64; ++k)
            acc_step(a1, sm + OFF_WIH1 + k * 256 + jw, sm + OFF_H0 + k * HSTRIDE + hoff);

        // ---------- phase F: cell1 -> h1 (no bar: h1 writes are disjoint from
        // E's h0/Wih1 reads and A(t+1)'s h0/xs reads; first h1 reader is
        // C(t+1), fenced by bar1(t+1)) ----------
        #pragma unroll
        for (int p = 0; p < 4; ++p) {
            ULL hp = cell_pair(a1, p, c1[p]);
            *(ULL*)(h1dst + 2 * p) = hp;
        }
    }

    __syncthreads();       // final h1 visible

    // ---------- FC head: out[b] = h1[b] . Wfc + bfc ----------
    if (tid < NBATCH_BLK) {
        float acc2 = __ldg(bfc);
        #pragma unroll 8
        for (int k = 0; k < 64; ++k)
            acc2 += sm[OFF_H1 + k * HSTRIDE + tid] * sm[OFF_WFC + k];
        out[Bb + tid] = acc2;
    }
}

extern "C" void kernel_launch(void* const* d_in, const int* in_sizes, int n_in,
                              void* d_out, int out_size) {
    (void)in_sizes; (void)n_in; (void)out_size;
    const float* x    = (const float*)d_in[0];
    const float* Wih0 = (const float*)d_in[1];
    const float* Whh0 = (const float*)d_in[2];
    const float* bih0 = (const float*)d_in[3];
    const float* bhh0 = (const float*)d_in[4];
    const float* Wih1 = (const float*)d_in[5];
    const float* Whh1 = (const float*)d_in[6];
    const float* bih1 = (const float*)d_in[7];
    const float* bhh1 = (const float*)d_in[8];
    const float* Wfc  = (const float*)d_in[9];
    const float* bfc  = (const float*)d_in[10];
    float* out = (float*)d_out;

    cudaFuncSetAttribute(lstm_kernel,
                         cudaFuncAttributeMaxDynamicSharedMemorySize, SMEM_BYTES);
    lstm_kernel<<<B / NBATCH_BLK, NTHREADS, SMEM_BYTES>>>(
        x, Wih0, Whh0, bih0, bhh0, Wih1, Whh1, bih1, bhh1, Wfc, bfc, out);
}

// round 17
// speedup vs baseline: 1.6387x; 1.1516x over previous
#include <cuda_runtime.h>
#include <cuda_bf16.h>
#include <cstdint>

// LSTMModel: B=4096, T=512, D=8, H=64, 2 layers + FC(64->1)
//
// R17 = R8 (best: 4542us) with ONE change: the three in-loop block-wide
// __syncthreads are replaced by per-group named barriers (bar.sync 1+g, 64).
//
// Why it's legal: batch group g's h0/h1 rows (columns g*8..g*8+7 of every
// HSTRIDE row) and its x-stage slots (bl in [8g,8g+7]) are written and read
// ONLY by threads 64g..64g+63 (warps 2g, 2g+1). Weights are read-only after
// init (global sync). So cross-group ordering is never required inside the
// T loop; a 64-thread barrier per group gives the full fence each group needs.
//
// Why it's fast: groups decouple and drift out of phase. Each SMSP hosts
// warps from two DIFFERENT groups (warp w and w+4), so MUFU-heavy cell
// phases of one group overlap FFMA-heavy GEMM phases of the other, and
// barrier skew stops being globally amplified 8-wide.

#define ULL unsigned long long

static __device__ __forceinline__ ULL pk2(float v) {
    ULL r; asm("mov.b64 %0, {%1, %1};" : "=l"(r) : "f"(v)); return r;
}
static __device__ __forceinline__ ULL pkf2(float a, float b) {
    ULL r; asm("mov.b64 %0, {%1, %2};" : "=l"(r) : "f"(a), "f"(b)); return r;
}
static __device__ __forceinline__ float2 upk(ULL v) {
    float2 f; asm("mov.b64 {%0, %1}, %2;" : "=f"(f.x), "=f"(f.y) : "l"(v)); return f;
}
static __device__ __forceinline__ ULL ffma2(ULL a, ULL b, ULL c) {
    ULL d; asm("fma.rn.f32x2 %0, %1, %2, %3;" : "=l"(d) : "l"(a), "l"(b), "l"(c)); return d;
}
static __device__ __forceinline__ float ex2f(float x) {
    float r; asm("ex2.approx.f32 %0, %1;" : "=f"(r) : "f"(x)); return r;
}
static __device__ __forceinline__ float rcpf(float x) {
    float r; asm("rcp.approx.f32 %0, %1;" : "=f"(r) : "f"(x)); return r;
}
static __device__ __forceinline__ float sigm(float x) {
    return rcpf(1.0f + ex2f(-1.4426950408889634f * x));
}
static __device__ __forceinline__ float tanh_fast(float x) {
    float ax = fabsf(x);
    float p = ex2f(-2.8853900817779268f * ax);
    float r = (1.0f - p) * rcpf(1.0f + p);
    return copysignf(r, x);
}
// group-local barrier: 64 threads (2 warps) of group g rendezvous on id 1+g
static __device__ __forceinline__ void group_bar(int g) {
    asm volatile("bar.sync %0, 64;" :: "r"(1 + g) : "memory");
}

static constexpr int B = 4096;
static constexpr int T = 512;
static constexpr int D = 8;
static constexpr int NBATCH_BLK = 32;
static constexpr int NTHREADS = 256;
static constexpr int HSTRIDE = 36;      // padded row stride (floats) for h state

// smem float offsets (identical to R3/R8)
static constexpr int OFF_WIH0 = 0;                    //  8*256
static constexpr int OFF_WHH0 = OFF_WIH0 + 2048;      // 64*256
static constexpr int OFF_WIH1 = OFF_WHH0 + 16384;     // 64*256
static constexpr int OFF_WHH1 = OFF_WIH1 + 16384;     // 64*256
static constexpr int OFF_B0   = OFF_WHH1 + 16384;     // 256
static constexpr int OFF_B1   = OFF_B0 + 256;         // 256
static constexpr int OFF_WFC  = OFF_B1 + 256;         // 64
static constexpr int OFF_H0   = OFF_WFC + 64;         // 64*36
static constexpr int OFF_H1   = OFF_H0 + 64 * HSTRIDE;// 64*36
static constexpr int OFF_XS   = OFF_H1 + 64 * HSTRIDE;// 2*256
static constexpr int SMEM_FLOATS = OFF_XS + 512;
static constexpr int SMEM_BYTES = SMEM_FLOATS * 4;    // 227,584 B

// Accumulate 4 gates x 4 batch-pairs from one k-slice into a[q*4+p].
static __device__ __forceinline__ void acc_step(ULL (&a)[16],
                                                const float* __restrict__ wb,
                                                const float* __restrict__ hb) {
    float4 w = *(const float4*)(wb);
    ulonglong2 hA = *(const ulonglong2*)(hb);
    ulonglong2 hB = *(const ulonglong2*)(hb + 4);
    ULL h0 = hA.x, h1 = hA.y, h2 = hB.x, h3 = hB.y;
    ULL w0 = pk2(w.x), w1 = pk2(w.y), w2 = pk2(w.z), w3 = pk2(w.w);
    a[0]  = ffma2(w0, h0, a[0]);  a[1]  = ffma2(w0, h1, a[1]);
    a[2]  = ffma2(w0, h2, a[2]);  a[3]  = ffma2(w0, h3, a[3]);
    a[4]  = ffma2(w1, h0, a[4]);  a[5]  = ffma2(w1, h1, a[5]);
    a[6]  = ffma2(w1, h2, a[6]);  a[7]  = ffma2(w1, h3, a[7]);
    a[8]  = ffma2(w2, h0, a[8]);  a[9]  = ffma2(w2, h1, a[9]);
    a[10] = ffma2(w2, h2, a[10]); a[11] = ffma2(w2, h3, a[11]);
    a[12] = ffma2(w3, h0, a[12]); a[13] = ffma2(w3, h1, a[13]);
    a[14] = ffma2(w3, h2, a[14]); a[15] = ffma2(w3, h3, a[15]);
}

static __device__ __forceinline__ void init_acc(ULL (&a)[16], float4 bz) {
    ULL bi = pk2(bz.x), bf = pk2(bz.y), bg = pk2(bz.z), bo = pk2(bz.w);
    a[0] = a[1] = a[2] = a[3] = bi;
    a[4] = a[5] = a[6] = a[7] = bf;
    a[8] = a[9] = a[10] = a[11] = bg;
    a[12] = a[13] = a[14] = a[15] = bo;
}

// LSTM cell for one batch-pair p. Returns packed h, updates packed c.
static __device__ __forceinline__ ULL cell_pair(const ULL (&a)[16], int p, ULL& c) {
    float2 i2 = upk(a[p]), f2 = upk(a[4 + p]), g2 = upk(a[8 + p]), o2 = upk(a[12 + p]);
    float2 c2 = upk(c);
    float i0 = sigm(i2.x), f0 = sigm(f2.x), g0 = tanh_fast(g2.x), o0 = sigm(o2.x);
    float i1 = sigm(i2.y), f1 = sigm(f2.y), g1 = tanh_fast(g2.y), o1 = sigm(o2.y);
    float cn0 = f0 * c2.x + i0 * g0;
    float cn1 = f1 * c2.y + i1 * g1;
    c = pkf2(cn0, cn1);
    return pkf2(o0 * tanh_fast(cn0), o1 * tanh_fast(cn1));
}

extern __shared__ float sm[];

__global__ void __launch_bounds__(NTHREADS, 1)
lstm_kernel(const float* __restrict__ x,
            const float* __restrict__ Wih0, const float* __restrict__ Whh0,
            const float* __restrict__ bih0, const float* __restrict__ bhh0,
            const float* __restrict__ Wih1, const float* __restrict__ Whh1,
            const float* __restrict__ bih1, const float* __restrict__ bhh1,
            const float* __restrict__ Wfc,  const float* __restrict__ bfc,
            float* __restrict__ out)
{
    const int tid = threadIdx.x;
    const int j = tid & 63;        // hidden unit
    const int g = tid >> 6;        // group (0..3): batch 8g..8g+7 (warps 2g,2g+1)
    const int Bb = blockIdx.x * NBATCH_BLK;

    // ---- load + transpose weights into smem (R8 layout) ----
    for (int idx = tid; idx < 2048; idx += NTHREADS) {
        int d = idx >> 8, r = idx & 255, jj = r >> 2, q = r & 3;
        sm[OFF_WIH0 + idx] = Wih0[(q * 64 + jj) * 8 + d];
    }
    for (int idx = tid; idx < 16384; idx += NTHREADS) {
        int k = idx >> 8, r = idx & 255, jj = r >> 2, q = r & 3;
        int row = (q * 64 + jj) * 64 + k;
        sm[OFF_WHH0 + idx] = Whh0[row];
        sm[OFF_WIH1 + idx] = Wih1[row];
        sm[OFF_WHH1 + idx] = Whh1[row];
    }
    {
        int jj = tid >> 2, q = tid & 3;
        sm[OFF_B0 + tid] = bih0[q * 64 + jj] + bhh0[q * 64 + jj];
        sm[OFF_B1 + tid] = bih1[q * 64 + jj] + bhh1[q * 64 + jj];
    }
    if (tid < 64) sm[OFF_WFC + tid] = Wfc[tid];
    for (int idx = tid; idx < 2 * 64 * HSTRIDE; idx += NTHREADS)
        sm[OFF_H0 + idx] = 0.0f;   // zero h0 and h1 (contiguous)

    // x prefetch mapping: thread loads x[Bb + bl][t][dl]; bl in [8g, 8g+7],
    // so each group's x-stage slots are written by its own threads only.
    const int bl = tid >> 3;       // 0..31
    const int dl = tid & 7;        // 0..7
    const float* xptr = x + (size_t)(Bb + bl) * (T * D) + dl;
    float x0 = __ldg(xptr);        // t = 0
    __syncthreads();               // weights/bias/h-zero visible (global, once)
    sm[OFF_XS + dl * 32 + bl] = x0;

    ULL c0[4] = {0, 0, 0, 0};      // packed cell state, layer 0 (4 pairs)
    ULL c1[4] = {0, 0, 0, 0};      // layer 1

    const int hoff = g * 8;        // float offset of this group's 4 pairs
    float* h0dst = sm + OFF_H0 + j * HSTRIDE + hoff;
    float* h1dst = sm + OFF_H1 + j * HSTRIDE + hoff;
    const float4 b0v = *(const float4*)(sm + OFF_B0 + j * 4);
    const float4 b1v = *(const float4*)(sm + OFF_B1 + j * 4);
    const int jw = j * 4;

    __syncthreads();               // x stage for t=0 visible (global, once)

    ULL a0[16], a1[16];

    for (int t = 0; t < T; ++t) {
        const int cur = (t & 1) * 256;
        const int nxt = 256 - cur;
        float xn = 0.0f;
        if (t + 1 < T) xn = __ldg(xptr + (t + 1) * D);

        // ---------- phase A: z0 = x@Wih0^T + h0_old@Whh0^T ----------
        init_acc(a0, b0v);
        #pragma unroll
        for (int d = 0; d < D; ++d)
            acc_step(a0, sm + OFF_WIH0 + d * 256 + jw, sm + OFF_XS + cur + d * 32 + hoff);
        #pragma unroll 8
        for (int k = 0; k < 64; ++k)
            acc_step(a0, sm + OFF_WHH0 + k * 256 + jw, sm + OFF_H0 + k * HSTRIDE + hoff);

        group_bar(g);   // bar1: group's h0_old + xs(cur) reads done; F(t-1) fenced

        // ---------- phase C: z1 += Whh1@h1_old, interleaved with cell0 ----------
        init_acc(a1, b1v);
        #pragma unroll
        for (int p = 0; p < 4; ++p) {
            #pragma unroll
            for (int k = p * 16; k < p * 16 + 16; ++k)
                acc_step(a1, sm + OFF_WHH1 + k * 256 + jw, sm + OFF_H1 + k * HSTRIDE + hoff);
            ULL hp = cell_pair(a0, p, c0[p]);
            *(ULL*)(h0dst + 2 * p) = hp;
        }
        sm[OFF_XS + nxt + dl * 32 + bl] = xn;   // stage next x (group-local slots)

        group_bar(g);   // bar2: group's h0_new + xs(next) visible; h1_old reads done

        // ---------- phase E: z1 += Wih1@h0_new ----------
        #pragma unroll 8
        for (int k = 0; k < 64; ++k)
            acc_step(a1, sm + OFF_WIH1 + k * 256 + jw, sm + OFF_H0 + k * HSTRIDE + hoff);

        group_bar(g);   // bar3: all z1 inputs consumed

        // ---------- phase F: cell1 -> h1 (overlaps other groups' phases) ----------
        #pragma unroll
        for (int p = 0; p < 4; ++p) {
            ULL hp = cell_pair(a1, p, c1[p]);
            *(ULL*)(h1dst + 2 * p) = hp;
        }
        // no trailing barrier: within the group, next A reads only h0/xs;
        // C(t+1)'s h1 reads are fenced by bar1(t+1).
    }

    __syncthreads();       // global: all groups' final h1 visible

    // ---------- FC head: out[b] = h1[b] . Wfc + bfc ----------
    if (tid < NBATCH_BLK) {
        float acc2 = __ldg(bfc);
        #pragma unroll 8
        for (int k = 0; k < 64; ++k)
            acc2 += sm[OFF_H1 + k * HSTRIDE + tid] * sm[OFF_WFC + k];
        out[Bb + tid] = acc2;
    }
}

extern "C" void kernel_launch(void* const* d_in, const int* in_sizes, int n_in,
                              void* d_out, int out_size) {
    (void)in_sizes; (void)n_in; (void)out_size;
    const float* x    = (const float*)d_in[0];
    const float* Wih0 = (const float*)d_in[1];
    const float* Whh0 = (const float*)d_in[2];
    const float* bih0 = (const float*)d_in[3];
    const float* bhh0 = (const float*)d_in[4];
    const float* Wih1 = (const float*)d_in[5];
    const float* Whh1 = (const float*)d_in[6];
    const float* bih1 = (const float*)d_in[7];
    const float* bhh1 = (const float*)d_in[8];
    const float* Wfc  = (const float*)d_in[9];
    const float* bfc  = (const float*)d_in[10];
    float* out = (float*)d_out;

    cudaFuncSetAttribute(lstm_kernel,
                         cudaFuncAttributeMaxDynamicSharedMemorySize, SMEM_BYTES);
    lstm_kernel<<<B / NBATCH_BLK, NTHREADS, SMEM_BYTES>>>(
        x, Wih0, Whh0, bih0, bhh0, Wih1, Whh1, bih1, bhh1, Wfc, bfc, out);
}